// round 17
// baseline (speedup 1.0000x reference)
#include <cuda_runtime.h>
#include <cuda_fp16.h>
#include <cstdint>
#include <math.h>

#define BBATCH 4
#define TT 1024
#define EE 1024
#define HH 16
#define DDIM 64
#define E3 3072
#define MTOK (BBATCH*TT)   // 4096

// Scratch (fp16): qkv split [3][B][H][T][D], attention outputs (B,T,E),
// pre-converted fp16 copies of all six inputs.
__device__ __half g_s1[3ull * BBATCH * HH * TT * DDIM];
__device__ __half g_s2[3ull * BBATCH * HH * TT * DDIM];
__device__ __half g_xo[(size_t)MTOK * EE];
__device__ __half g_yo[(size_t)MTOK * EE];
__device__ __half g_hx[(size_t)MTOK * EE];
__device__ __half g_hy[(size_t)MTOK * EE];
__device__ __half g_hwq1[(size_t)E3 * EE];
__device__ __half g_hwq2[(size_t)E3 * EE];
__device__ __half g_hwo1[(size_t)EE * EE];
__device__ __half g_hwo2[(size_t)EE * EE];

// ---------------------------------------------------------------------------
// helpers (sm_75/80-level PTX: valid on plain compute_103 target)
// ---------------------------------------------------------------------------
__device__ __forceinline__ uint32_t smem_u32(const void* p) {
    uint32_t a;
    asm("{ .reg .u64 t; cvta.to.shared.u64 t, %1; cvt.u32.u64 %0, t; }" : "=r"(a) : "l"(p));
    return a;
}
__device__ __forceinline__ void cp16(uint32_t dst, const void* src) {
    asm volatile("cp.async.cg.shared.global [%0], [%1], 16;" :: "r"(dst), "l"(src));
}
__device__ __forceinline__ void cp_commit() {
    asm volatile("cp.async.commit_group;" ::: "memory");
}
template<int N>
__device__ __forceinline__ void cp_wait() {
    asm volatile("cp.async.wait_group %0;" :: "n"(N) : "memory");
}
__device__ __forceinline__ void mma_f16(float* d, const uint32_t* a, const uint32_t* b) {
    asm volatile(
        "mma.sync.aligned.m16n8k16.row.col.f32.f16.f16.f32 "
        "{%0,%1,%2,%3}, {%4,%5,%6,%7}, {%8,%9}, {%0,%1,%2,%3};"
        : "+f"(d[0]), "+f"(d[1]), "+f"(d[2]), "+f"(d[3])
        : "r"(a[0]), "r"(a[1]), "r"(a[2]), "r"(a[3]), "r"(b[0]), "r"(b[1]));
}
__device__ __forceinline__ void ldmx4(uint32_t& r0, uint32_t& r1, uint32_t& r2,
                                      uint32_t& r3, uint32_t addr) {
    asm volatile("ldmatrix.sync.aligned.m8n8.x4.shared.b16 {%0,%1,%2,%3}, [%4];"
        : "=r"(r0), "=r"(r1), "=r"(r2), "=r"(r3) : "r"(addr));
}
__device__ __forceinline__ void ldmx4t(uint32_t& r0, uint32_t& r1, uint32_t& r2,
                                       uint32_t& r3, uint32_t addr) {
    asm volatile("ldmatrix.sync.aligned.m8n8.x4.trans.shared.b16 {%0,%1,%2,%3}, [%4];"
        : "=r"(r0), "=r"(r1), "=r"(r2), "=r"(r3) : "r"(addr));
}
__device__ __forceinline__ uint32_t pack_h2(float a, float b) {
    __half2 h = __floats2half2_rn(a, b);
    return *(uint32_t*)&h;
}

// ---------------------------------------------------------------------------
// Pre-convert fp32 -> fp16 (RN). Two tensors per launch (blockIdx.y).
// ---------------------------------------------------------------------------
__global__ void __launch_bounds__(256) cvt_h_kernel(
    const float4* __restrict__ s0, const float4* __restrict__ s1v,
    uint2* __restrict__ d0, uint2* __restrict__ d1, int n4)
{
    const float4* s = blockIdx.y ? s1v : s0;
    uint2*        d = blockIdx.y ? d1  : d0;
    const int i = blockIdx.x * 256 + threadIdx.x;
    if (i < n4) {
        float4 v = s[i];
        uint2 o;
        o.x = pack_h2(v.x, v.y);
        o.y = pack_h2(v.z, v.w);
        d[i] = o;
    }
}

// ---------------------------------------------------------------------------
// fp16 mma.sync GEMM, batched over blockIdx.z:  C = A(M,K) @ B^T (B = (N,K)).
// 128x128x64(half) CTA tile, 8 warps (2x4), 3-stage cp.async pipeline.
// Fragments via ldmatrix.x4 (6 per k-step instead of 24 scalar LDS).
// Half pitch 72 (row stride 144 B): ldmatrix row banks 4r mod 32 -> conflict-free.
// SPLIT: scatter fp16 into [kk][b][h][t][dd]; else fp32 C.
// ---------------------------------------------------------------------------
#define BM 128
#define BN 128
#define BKH 64
#define PKH 72
#define PKW 36
#define NKT16 (EE / BKH)               // 16
#define STAGE_H ((BM + BN) * PKH)      // 18432 halves
#define GSMEM_B (3 * STAGE_H * 2)      // 110592 B

template<bool SPLIT>
__global__ void __launch_bounds__(256, 2) gemm_f16_kernel(
    const __half* __restrict__ A0, const __half* __restrict__ A1,
    const __half* __restrict__ B0, const __half* __restrict__ B1,
    void* __restrict__ C0, void* __restrict__ C1, int N)
{
    extern __shared__ char smc[];
    const __half* A = blockIdx.z ? A1 : A0;
    const __half* Bm = blockIdx.z ? B1 : B0;
    void* C = blockIdx.z ? C1 : C0;

    const int tid = threadIdx.x;
    const int lid = tid & 31;
    const int wid = tid >> 5;
    const int warp_m = wid & 1;
    const int warp_n = wid >> 1;
    const int g = lid >> 2;
    const int q = lid & 3;
    const int row0 = blockIdx.y * BM;
    const int col0 = blockIdx.x * BN;

    const uint32_t sbase = smem_u32(smc);

    // ldmatrix per-lane address components (non-trans x4 layout):
    // lanes 0-7: (r, kblk0), 8-15: (r+8, kblk0), 16-23: (r, kblk1), 24-31: (r+8, kblk1)
    const int lr = lid & 7;
    const int lb = (lid >> 3) & 1;
    const int lk = (lid >> 4) & 1;
    const uint32_t aoff = (uint32_t)((warp_m * 64 + lr + lb * 8) * PKH + lk * 8) * 2u;
    const uint32_t boff = (uint32_t)((warp_n * 32 + lr + lb * 8) * PKH + lk * 8) * 2u;

    auto issue = [&](int stg, int kt) {
        const uint32_t s_a = sbase + (uint32_t)(stg * STAGE_H) * 2u;
        const uint32_t s_b = s_a + (uint32_t)(BM * PKH) * 2u;
        #pragma unroll
        for (int i = 0; i < 4; ++i) {
            const int idx = tid + 256 * i;          // 0..1023
            const int r = idx >> 3;                 // row 0..127
            const int c = (idx & 7) * 8;            // half col 0,8,..,56
            cp16(s_a + (uint32_t)(r * PKH + c) * 2u,
                 A + (size_t)(row0 + r) * EE + kt * BKH + c);
            cp16(s_b + (uint32_t)(r * PKH + c) * 2u,
                 Bm + (size_t)(col0 + r) * EE + kt * BKH + c);
        }
    };

    float acc[4][4][4];
    #pragma unroll
    for (int i = 0; i < 4; ++i)
        #pragma unroll
        for (int j = 0; j < 4; ++j)
            #pragma unroll
            for (int r = 0; r < 4; ++r) acc[i][j][r] = 0.f;

    #pragma unroll
    for (int s = 0; s < 2; ++s) { issue(s, s); cp_commit(); }

    for (int kt = 0; kt < NKT16; ++kt) {
        if (kt < NKT16 - 1) cp_wait<1>(); else cp_wait<0>();
        __syncthreads();

        if (kt + 2 < NKT16) { issue((kt + 2) % 3, kt + 2); cp_commit(); }

        const uint32_t s_a = sbase + (uint32_t)((kt % 3) * STAGE_H) * 2u;
        const uint32_t s_b = s_a + (uint32_t)(BM * PKH) * 2u;

        #pragma unroll
        for (int ks = 0; ks < 4; ++ks) {
            const uint32_t kso = (uint32_t)(ks * 16) * 2u;   // 16 halves per k-step
            uint32_t af[4][4], bf[4][2];
            #pragma unroll
            for (int im = 0; im < 4; ++im)
                ldmx4(af[im][0], af[im][1], af[im][2], af[im][3],
                      s_a + aoff + (uint32_t)(im * 16 * PKH) * 2u + kso);
            #pragma unroll
            for (int j2 = 0; j2 < 2; ++j2) {
                uint32_t r0, r1, r2, r3;
                ldmx4(r0, r1, r2, r3,
                      s_b + boff + (uint32_t)(j2 * 16 * PKH) * 2u + kso);
                bf[2*j2][0] = r0;   bf[2*j2][1] = r2;
                bf[2*j2+1][0] = r1; bf[2*j2+1][1] = r3;
            }
            #pragma unroll
            for (int im = 0; im < 4; ++im)
                #pragma unroll
                for (int jn = 0; jn < 4; ++jn)
                    mma_f16(acc[im][jn], af[im], bf[jn]);
        }
    }

    #pragma unroll
    for (int im = 0; im < 4; ++im) {
        #pragma unroll
        for (int jn = 0; jn < 4; ++jn) {
            const int mrow = row0 + warp_m * 64 + im * 16 + g;
            const int ncol = col0 + warp_n * 32 + jn * 8 + 2 * q;
            #pragma unroll
            for (int rg = 0; rg < 4; ++rg) {
                const int m = mrow + ((rg >> 1) << 3);
                const int n = ncol + (rg & 1);
                if (SPLIT) {
                    const int dd = n / 48;
                    const int rr = n - dd * 48;
                    const int kk = rr >> 4;
                    const int hh = rr & 15;
                    const int bb = m >> 10;
                    const int t  = m & 1023;
                    ((__half*)C)[((((size_t)kk * BBATCH + bb) * HH + hh) * TT + t) * DDIM + dd] =
                        __float2half_rn(acc[im][jn][rg]);
                } else {
                    ((float*)C)[(size_t)m * N + n] = acc[im][jn][rg];
                }
            }
        }
    }
}

// ---------------------------------------------------------------------------
// Dual-stream cross attention, fp16 mma.sync m16n8k16. (R16, passing — unchanged)
// ---------------------------------------------------------------------------
#define TQ 128
#define TK 64
#define AQ0 0
#define AK0 (TQ * PKW)                 // 4608 words
#define AV0 (AK0 + TK * PKW)           // 6912
#define AP0 (AV0 + TK * PKW)           // 9216
#define ASMW (AP0 + 4 * 32 * PKW)      // 13824 words = 55296 B

__global__ void __launch_bounds__(128, 2) attn_tc_kernel(
    const __half* __restrict__ s1, const __half* __restrict__ s2,
    __half* __restrict__ xo, __half* __restrict__ yo)
{
    extern __shared__ uint32_t smu[];
    const int tid = threadIdx.x;
    const int lid = tid & 31;
    const int w   = tid >> 5;
    const int g   = lid >> 2;
    const int q   = lid & 3;
    const int qt  = blockIdx.x;
    const int b   = blockIdx.y >> 4;
    const int h   = blockIdx.y & 15;
    const int st  = blockIdx.z;

    const __half* Qg = (st == 0) ? s2 : s1;
    const __half* Kg = (st == 0) ? s1 : s2;
    __half*       Og = (st == 0) ? xo : yo;

    const size_t plane = (size_t)BBATCH * HH * TT * DDIM;
    const size_t bh    = ((size_t)b * HH + h) * TT * DDIM;
    const __half* Qb = Qg + bh + (size_t)qt * TQ * DDIM;
    const __half* Kb = Kg + plane + bh;
    const __half* Vb = Kg + 2 * plane + bh;

    const uint32_t vbase = smem_u32(smu) + AV0 * 4;

    const int sel = lid >> 3;
    const int lr8 = lid & 7;
    const int vrow = lr8 + ((sel & 1) << 3);
    const int vcolw = (sel >> 1) << 2;

    {
        const float4* qb4 = (const float4*)Qb;
        #pragma unroll
        for (int i = 0; i < 8; ++i) {
            const int j = tid + 128 * i;
            const int t = j >> 3, cw = (j & 7) * 4;
            *reinterpret_cast<float4*>(&smu[AQ0 + t * PKW + cw]) = qb4[j];
        }
    }

    float oacc[2][8][4];
    #pragma unroll
    for (int im = 0; im < 2; ++im)
        #pragma unroll
        for (int nt = 0; nt < 8; ++nt)
            #pragma unroll
            for (int r = 0; r < 4; ++r) oacc[im][nt][r] = 0.f;
    float mrow[2][2] = {{-1e30f, -1e30f}, {-1e30f, -1e30f}};
    float lrow[2][2] = {{0.f, 0.f}, {0.f, 0.f}};

    uint32_t* Pw = smu + AP0 + w * 32 * PKW;
    const int mr = w * 32;

    float4 kreg[4], vreg[4];
    auto ldkv = [&](int kt) {
        const float4* kb4 = (const float4*)(Kb + (size_t)kt * TK * DDIM);
        const float4* vb4 = (const float4*)(Vb + (size_t)kt * TK * DDIM);
        #pragma unroll
        for (int i = 0; i < 4; ++i) {
            kreg[i] = kb4[tid + 128 * i];
            vreg[i] = vb4[tid + 128 * i];
        }
    };
    ldkv(0);

    for (int kt = 0; kt < TT / TK; ++kt) {
        __syncthreads();
        #pragma unroll
        for (int i = 0; i < 4; ++i) {
            const int j = tid + 128 * i;
            const int t = j >> 3, cw = (j & 7) * 4;
            *reinterpret_cast<float4*>(&smu[AK0 + t * PKW + cw]) = kreg[i];
            *reinterpret_cast<float4*>(&smu[AV0 + t * PKW + cw]) = vreg[i];
        }
        __syncthreads();
        if (kt + 1 < TT / TK) ldkv(kt + 1);

        float sacc[2][8][4];
        #pragma unroll
        for (int im = 0; im < 2; ++im)
            #pragma unroll
            for (int nt = 0; nt < 8; ++nt)
                #pragma unroll
                for (int r = 0; r < 4; ++r) sacc[im][nt][r] = 0.f;

        #pragma unroll
        for (int ks = 0; ks < 4; ++ks) {
            const int k0 = ks * 8;
            uint32_t af[2][4];
            #pragma unroll
            for (int im = 0; im < 2; ++im) {
                const int row = mr + 16 * im;
                af[im][0] = smu[AQ0 + (row + g) * PKW + k0 + q];
                af[im][1] = smu[AQ0 + (row + g + 8) * PKW + k0 + q];
                af[im][2] = smu[AQ0 + (row + g) * PKW + k0 + q + 4];
                af[im][3] = smu[AQ0 + (row + g + 8) * PKW + k0 + q + 4];
            }
            #pragma unroll
            for (int nt = 0; nt < 8; ++nt) {
                uint32_t bf[2];
                bf[0] = smu[AK0 + (nt * 8 + g) * PKW + k0 + q];
                bf[1] = smu[AK0 + (nt * 8 + g) * PKW + k0 + q + 4];
                mma_f16(sacc[0][nt], af[0], bf);
                mma_f16(sacc[1][nt], af[1], bf);
            }
        }

        #pragma unroll
        for (int im = 0; im < 2; ++im) {
            #pragma unroll
            for (int i = 0; i < 2; ++i) {
                float tm = -1e30f;
                #pragma unroll
                for (int nt = 0; nt < 8; ++nt) {
                    sacc[im][nt][2*i]   *= 0.125f;
                    sacc[im][nt][2*i+1] *= 0.125f;
                    tm = fmaxf(tm, fmaxf(sacc[im][nt][2*i], sacc[im][nt][2*i+1]));
                }
                tm = fmaxf(tm, __shfl_xor_sync(0xffffffffu, tm, 1));
                tm = fmaxf(tm, __shfl_xor_sync(0xffffffffu, tm, 2));
                const float newm = fmaxf(mrow[im][i], tm);
                float rs = 0.f;
                #pragma unroll
                for (int nt = 0; nt < 8; ++nt) {
                    const float p0 = __expf(sacc[im][nt][2*i]   - newm);
                    const float p1 = __expf(sacc[im][nt][2*i+1] - newm);
                    sacc[im][nt][2*i] = p0; sacc[im][nt][2*i+1] = p1;
                    rs += p0 + p1;
                }
                rs += __shfl_xor_sync(0xffffffffu, rs, 1);
                rs += __shfl_xor_sync(0xffffffffu, rs, 2);
                const float sc = __expf(mrow[im][i] - newm);
                lrow[im][i] = lrow[im][i] * sc + rs;
                mrow[im][i] = newm;
                #pragma unroll
                for (int nt = 0; nt < 8; ++nt) {
                    oacc[im][nt][2*i]   *= sc;
                    oacc[im][nt][2*i+1] *= sc;
                }
            }
        }

        #pragma unroll
        for (int im = 0; im < 2; ++im) {
            const int r0 = 16 * im;
            #pragma unroll
            for (int nt = 0; nt < 8; ++nt) {
                Pw[(r0 + g) * PKW + nt * 4 + q]     = pack_h2(sacc[im][nt][0], sacc[im][nt][1]);
                Pw[(r0 + g + 8) * PKW + nt * 4 + q] = pack_h2(sacc[im][nt][2], sacc[im][nt][3]);
            }
        }
        __syncwarp();

        #pragma unroll
        for (int ks = 0; ks < 4; ++ks) {
            const int k0 = ks * 8;
            uint32_t pa[2][4];
            #pragma unroll
            for (int im = 0; im < 2; ++im) {
                const int r0 = 16 * im;
                pa[im][0] = Pw[(r0 + g) * PKW + k0 + q];
                pa[im][1] = Pw[(r0 + g + 8) * PKW + k0 + q];
                pa[im][2] = Pw[(r0 + g) * PKW + k0 + q + 4];
                pa[im][3] = Pw[(r0 + g + 8) * PKW + k0 + q + 4];
            }
            const uint32_t arow = vbase + (uint32_t)((ks * 16 + vrow) * PKW) * 4u;
            #pragma unroll
            for (int ntp = 0; ntp < 4; ++ntp) {
                uint32_t v0, v1, v2, v3;
                ldmx4t(v0, v1, v2, v3, arow + (uint32_t)(ntp * 8 + vcolw) * 4u);
                uint32_t bfa[2] = {v0, v1}, bfb[2] = {v2, v3};
                mma_f16(oacc[0][2*ntp],     pa[0], bfa);
                mma_f16(oacc[1][2*ntp],     pa[1], bfa);
                mma_f16(oacc[0][2*ntp + 1], pa[0], bfb);
                mma_f16(oacc[1][2*ntp + 1], pa[1], bfb);
            }
        }
    }

    #pragma unroll
    for (int im = 0; im < 2; ++im) {
        #pragma unroll
        for (int i = 0; i < 2; ++i) {
            const float inv = 1.f / lrow[im][i];
            const int m = qt * TQ + mr + 16 * im + 8 * i + g;
            __half* orow = Og + ((size_t)b * TT + m) * EE + h * 64;
            #pragma unroll
            for (int nt = 0; nt < 8; ++nt) {
                uint32_t hv = pack_h2(oacc[im][nt][2*i] * inv, oacc[im][nt][2*i+1] * inv);
                *(uint32_t*)(orow + nt * 8 + 2 * q) = hv;
            }
        }
    }
}

// ---------------------------------------------------------------------------
extern "C" void kernel_launch(void* const* d_in, const int* in_sizes, int n_in,
                              void* d_out, int out_size)
{
    const float* x     = (const float*)d_in[0];
    const float* y     = (const float*)d_in[1];
    const float* Wqkv1 = (const float*)d_in[2];
    const float* Wqkv2 = (const float*)d_in[3];
    const float* Wout1 = (const float*)d_in[4];
    const float* Wout2 = (const float*)d_in[5];
    float* out = (float*)d_out;

    __half *s1, *s2, *xo, *yo, *hx, *hy, *hwq1, *hwq2, *hwo1, *hwo2;
    cudaGetSymbolAddress((void**)&s1, g_s1);
    cudaGetSymbolAddress((void**)&s2, g_s2);
    cudaGetSymbolAddress((void**)&xo, g_xo);
    cudaGetSymbolAddress((void**)&yo, g_yo);
    cudaGetSymbolAddress((void**)&hx, g_hx);
    cudaGetSymbolAddress((void**)&hy, g_hy);
    cudaGetSymbolAddress((void**)&hwq1, g_hwq1);
    cudaGetSymbolAddress((void**)&hwq2, g_hwq2);
    cudaGetSymbolAddress((void**)&hwo1, g_hwo1);
    cudaGetSymbolAddress((void**)&hwo2, g_hwo2);

    // Pre-convert all six inputs to fp16 (paired launches)
    const int n4_act = MTOK * EE / 4;
    const int n4_wq  = E3 * EE / 4;
    const int n4_wo  = EE * EE / 4;
    cvt_h_kernel<<<dim3((n4_act + 255) / 256, 2), 256>>>(
        (const float4*)x, (const float4*)y, (uint2*)hx, (uint2*)hy, n4_act);
    cvt_h_kernel<<<dim3((n4_wq + 255) / 256, 2), 256>>>(
        (const float4*)Wqkv1, (const float4*)Wqkv2, (uint2*)hwq1, (uint2*)hwq2, n4_wq);
    cvt_h_kernel<<<dim3((n4_wo + 255) / 256, 2), 256>>>(
        (const float4*)Wout1, (const float4*)Wout2, (uint2*)hwo1, (uint2*)hwo2, n4_wo);

    cudaFuncSetAttribute(gemm_f16_kernel<true>,
                         cudaFuncAttributeMaxDynamicSharedMemorySize, GSMEM_B);
    cudaFuncSetAttribute(gemm_f16_kernel<false>,
                         cudaFuncAttributeMaxDynamicSharedMemorySize, GSMEM_B);

    // QKV projections for BOTH streams (fp16 mma + ldmatrix), split to [3][B][H][T][D]
    gemm_f16_kernel<true><<<dim3(E3 / BN, MTOK / BM, 2), 256, GSMEM_B>>>(
        hx, hy, hwq1, hwq2, s1, s2, E3);

    // Cross attention (fp16 mma flash)
    const int asmem = ASMW * 4;   // 55296 B
    cudaFuncSetAttribute(attn_tc_kernel,
                         cudaFuncAttributeMaxDynamicSharedMemorySize, asmem);
    attn_tc_kernel<<<dim3(TT / TQ, BBATCH * HH, 2), 128, asmem>>>(s1, s2, xo, yo);

    // Output projections for BOTH streams (fp16 mma, fp32 out)
    gemm_f16_kernel<false><<<dim3(EE / BN, MTOK / BM, 2), 256, GSMEM_B>>>(
        xo, yo, hwo1, hwo2, out, out + (size_t)MTOK * EE, EE);
}